// round 3
// baseline (speedup 1.0000x reference)
#include <cuda_runtime.h>

#define NQ 22
#define DIM (1u << 22)

// ---------------- device scratch (static: no allocation) ----------------
__device__ float g_psi0[DIM];          // logical state 0 (real amplitudes)
__device__ float g_psi1[DIM];          // logical state 1
__device__ float g_cs1[NQ][2];         // layer-1 (second layer) cos/sin of theta/2
__device__ float g_Thi[2048];          // product table, x bits 11..21 (qubits 10..0)
__device__ float g_Tlo[2][2048];       // product table, x bits 0..10 (qubits 21..11), per state
__device__ float g_part[1024 * 22 * 5];// per-tile partial sums

// ---------------- kernel 1: angles + product tables ----------------
__global__ void k_prep(const float* __restrict__ theta) {
    __shared__ float cs0[NQ][2];
    int t = threadIdx.x;
    if (t < NQ) {
        float h0 = 0.5f * theta[t];         // layer 0, qubit t
        cs0[t][0] = cosf(h0);
        cs0[t][1] = sinf(h0);
        float h1 = 0.5f * theta[NQ + t];    // layer 1, qubit t
        g_cs1[t][0] = cosf(h1);
        g_cs1[t][1] = sinf(h1);
    }
    __syncthreads();
    for (int v = t; v < 2048; v += blockDim.x) {
        // Thi: index bit k (0..10) <-> x bit (11+k) <-> qubit 10-k. Qubit starts |0>.
        float ph = 1.f;
        #pragma unroll
        for (int k = 0; k < 11; k++) {
            int q = 10 - k;
            int bit = (v >> k) & 1;
            ph *= cs0[q][bit];
        }
        g_Thi[v] = ph;
        // Tlo: index bit k (0..10) <-> x bit k <-> qubit 21-k.
        // qubit 21 starts in |i> for logical state i: RY|1> = (-s, c).
        float p0 = 1.f, p1 = 1.f;
        #pragma unroll
        for (int k = 0; k < 11; k++) {
            int q = 21 - k;
            int bit = (v >> k) & 1;
            float f = cs0[q][bit];
            p0 *= f;
            float f1 = (q == 21) ? (bit ? cs0[21][0] : -cs0[21][1]) : f;
            p1 *= f1;
        }
        g_Tlo[0][v] = p0;
        g_Tlo[1][v] = p1;
    }
}

// ---------------- kernel 2: generate psi1 = P1 * (RY1 |init>) pointwise,
// then layer-2 RY butterflies on linear bits 12..0 (qubits 9..21), in smem ----
__global__ void k_genA() {
    __shared__ float s[8192];
    int bx = blockIdx.x;                 // 0..1023
    int st = bx >> 9;
    unsigned base = (unsigned)(bx & 511) << 13;
    const float* __restrict__ Tlo = g_Tlo[st];
    int t = threadIdx.x;                 // 512 threads

    for (int off = t; off < 8192; off += 512) {
        unsigned y = base + (unsigned)off;
        // x = L^{-1} y : x = (y ^ (y>>1)) with bits 20,21 corrected by y&1
        unsigned x = (y ^ (y >> 1)) ^ ((y & 1u) * 0x300000u);
        s[off] = __ldg(&g_Thi[x >> 11]) * __ldg(&Tlo[x & 2047u]);
    }
    __syncthreads();

    for (int b = 12; b >= 0; b--) {
        int q = 21 - b;                  // linear bit b <-> qubit 21-b
        float c = g_cs1[q][0], sn = g_cs1[q][1];
        unsigned lowm = (1u << b) - 1u;
        for (int p = t; p < 4096; p += 512) {
            unsigned o0 = (((unsigned)p & ~lowm) << 1) | ((unsigned)p & lowm);
            unsigned o1 = o0 | (1u << b);
            float a0 = s[o0], a1 = s[o1];
            s[o0] = c * a0 - sn * a1;
            s[o1] = sn * a0 + c * a1;
        }
        __syncthreads();
    }

    float* __restrict__ g = st ? g_psi1 : g_psi0;
    for (int off = t; off < 8192; off += 512)
        g[base + off] = s[off];
}

// ---------------- kernel 3: layer-2 RY butterflies on linear bits 13..21
// (qubits 8..0). Tile = 512 hi-combos x 16 contiguous, smem padded x17. ----
__global__ void k_passB() {
    __shared__ float s[512 * 17];
    int bx = blockIdx.x;                 // 0..1023
    int st = bx >> 9;
    unsigned mid = (unsigned)(bx & 511) << 4;   // bits 4..12
    float* __restrict__ g = st ? g_psi1 : g_psi0;
    int t = threadIdx.x;                 // 512 threads

    for (int i = t; i < 8192; i += 512) {
        int hi = i >> 4, lo = i & 15;
        s[hi * 17 + lo] = g[((unsigned)hi << 13) | mid | (unsigned)lo];
    }
    __syncthreads();

    for (int bb = 0; bb <= 8; bb++) {
        int q = 8 - bb;                  // global bit 13+bb <-> qubit 8-bb
        float c = g_cs1[q][0], sn = g_cs1[q][1];
        unsigned lowm = (1u << bb) - 1u;
        for (int p = t; p < 4096; p += 512) {
            int ph = p >> 4, lo = p & 15;
            unsigned h0 = (((unsigned)ph & ~lowm) << 1) | ((unsigned)ph & lowm);
            unsigned h1 = h0 | (1u << bb);
            float a0 = s[h0 * 17 + lo], a1 = s[h1 * 17 + lo];
            s[h0 * 17 + lo] = c * a0 - sn * a1;
            s[h1 * 17 + lo] = sn * a0 + c * a1;
        }
        __syncthreads();
    }

    for (int i = t; i < 8192; i += 512) {
        int hi = i >> 4, lo = i & 15;
        g[((unsigned)hi << 13) | mid | (unsigned)lo] = s[hi * 17 + lo];
    }
}

// ---------------- kernel 4: Pauli reductions with P2 folded in ----------------
// Per qubit m: flip mask d_m = L^{-1} e_m, prefix parity mask P_m.
// 5 sums per qubit: Adiff, A01, B01, Cdiff, C01. One warp per qubit.
__global__ void k_reduce() {
    __shared__ float s0[4096];
    __shared__ float s1[4096];
    unsigned tile = blockIdx.x;          // 0..1023
    unsigned base = tile << 12;
    int t = threadIdx.x;                 // 704 = 22 warps

    for (int off = t; off < 4096; off += 704) {
        s0[off] = g_psi0[base + off];
        s1[off] = g_psi1[base + off];
    }
    __syncthreads();

    int w = t >> 5, lane = t & 31;
    int m = w;                           // qubit index, 0..21
    unsigned d = (m <= 20) ? (3u << (20 - m)) : 0x300001u;
    unsigned dlow = d & 4095u, dhigh = d & ~4095u;
    unsigned P = (m == 0) ? 0x1FFFFFu
                          : (((1u << (m + 1)) - 1u) << (21 - m));
    unsigned Plow = P & 4095u;
    int sbase = __popc(base & P) & 1;

    float ad = 0.f, a01 = 0.f, b01 = 0.f, cd = 0.f, c01 = 0.f;
    for (int off = lane; off < 4096; off += 32) {
        float v0 = s0[off], v1 = s1[off];
        int par = (__popc((unsigned)off & Plow) ^ sbase) & 1;
        float zs = par ? -1.f : 1.f;     // zs = 1 - 2*z_m(w)
        cd  = fmaf(zs, v0 * v0 - v1 * v1, cd);
        c01 = fmaf(zs, v0 * v1, c01);
        float p0, p1;
        if (dhigh == 0u) {
            int po = off ^ (int)dlow;
            p0 = s0[po];
            p1 = s1[po];
        } else {
            unsigned gi = (base ^ dhigh) | ((unsigned)off ^ dlow);
            p0 = __ldg(&g_psi0[gi]);
            p1 = __ldg(&g_psi1[gi]);
        }
        ad += v0 * p0 - v1 * p1;
        float tt = v0 * p1;
        a01 += tt;
        b01 -= zs * tt;                  // B sign = (2z-1) = -zs
    }
    #pragma unroll
    for (int o = 16; o; o >>= 1) {
        ad  += __shfl_xor_sync(0xffffffffu, ad,  o);
        a01 += __shfl_xor_sync(0xffffffffu, a01, o);
        b01 += __shfl_xor_sync(0xffffffffu, b01, o);
        cd  += __shfl_xor_sync(0xffffffffu, cd,  o);
        c01 += __shfl_xor_sync(0xffffffffu, c01, o);
    }
    if (lane == 0) {
        float* pp = &g_part[(tile * 22 + (unsigned)m) * 5];
        pp[0] = ad; pp[1] = a01; pp[2] = b01; pp[3] = cd; pp[4] = c01;
    }
}

// ---------------- kernel 5: final combine ----------------
__global__ void k_final(float* __restrict__ out) {
    __shared__ float sums[110];
    int t = threadIdx.x;                 // 128
    if (t < 110) {
        float acc = 0.f;
        for (int tile = 0; tile < 1024; tile++)
            acc += g_part[tile * 110 + t];
        sums[t] = acc;
    }
    __syncthreads();
    if (t == 0) {
        float loss = 0.f;
        for (int m = 0; m < 22; m++) {
            float ad  = sums[m * 5 + 0];
            float a01 = sums[m * 5 + 1];
            float b01 = sums[m * 5 + 2];
            float cd  = sums[m * 5 + 3];
            float c01 = sums[m * 5 + 4];
            // X: (A00-A11)^2/2 + 2*A01^2 ; Y: 2*B01^2 ; Z: (C00-C11)^2/2 + 2*C01^2
            loss += 0.5f * ad * ad + 2.f * a01 * a01
                  + 2.f * b01 * b01
                  + 0.5f * cd * cd + 2.f * c01 * c01;
        }
        out[0] = loss;
    }
}

extern "C" void kernel_launch(void* const* d_in, const int* in_sizes, int n_in,
                              void* d_out, int out_size) {
    const float* theta = (const float*)d_in[0];
    (void)in_sizes; (void)n_in; (void)out_size;
    k_prep<<<1, 1024>>>(theta);
    k_genA<<<1024, 512>>>();
    k_passB<<<1024, 512>>>();
    k_reduce<<<1024, 704>>>();
    k_final<<<1, 128>>>((float*)d_out);
}